// round 13
// baseline (speedup 1.0000x reference)
#include <cuda_runtime.h>
#include <cuda_fp16.h>
#include <math.h>
#include <stdint.h>

// ---------------- problem constants ----------------
#define N_HALF 4096
#define N2     8192
#define Dm     256
#define EPSN   1e-8f
#define NBLK   64            // 8192 / 128 row blocks
#define NPAIR  1056          // sum over bi of ceil((64-bi)/2)
#define GRID   148           // persistent CTAs

// ---------------- device scratch ----------------
__device__ __align__(16) __half gF[N2 * Dm];   // fp16 normalized rows (4MB, L2-resident)
// partials: slot o = "other" block; each (o,row) written exactly once
__device__ float g_pf [NBLK][N2];   // partial expsum (fixed shift C = 1/T)
__device__ float g_pmv[NBLK][N2];   // partial max sim
__device__ int   g_pmc[NBLK][N2];   // partial argmax col (global)
__device__ float g_tgt[N2];         // target logit per row
__device__ float g_redl[32];
__device__ int   g_redc[32];
__device__ int   g_ctr;             // finalize arrival counter (reset in normalize)

// ---------------- PTX helpers (sm_80-era: compile under compute_103) ------
__device__ __forceinline__ uint32_t smem_u32(const void* p) {
    uint32_t a;
    asm("{ .reg .u64 t; cvta.to.shared.u64 t, %1; cvt.u32.u64 %0, t; }" : "=r"(a) : "l"(p));
    return a;
}
__device__ __forceinline__ void cp16(uint32_t sdst, const void* gsrc) {
    asm volatile("cp.async.cg.shared.global [%0], [%1], 16;" :: "r"(sdst), "l"(gsrc) : "memory");
}
__device__ __forceinline__ void cp_commit() {
    asm volatile("cp.async.commit_group;" ::: "memory");
}
__device__ __forceinline__ void cp_wait0() {
    asm volatile("cp.async.wait_group 0;" ::: "memory");
}
__device__ __forceinline__ void ldm_x4(uint32_t* r, uint32_t addr) {
    asm volatile("ldmatrix.sync.aligned.m8n8.x4.shared.b16 {%0,%1,%2,%3}, [%4];"
        : "=r"(r[0]), "=r"(r[1]), "=r"(r[2]), "=r"(r[3]) : "r"(addr));
}
__device__ __forceinline__ void mma16816(float* d, const uint32_t* a, uint32_t b0, uint32_t b1) {
    asm volatile("mma.sync.aligned.m16n8k16.row.col.f32.f16.f16.f32 "
        "{%0,%1,%2,%3}, {%4,%5,%6,%7}, {%8,%9}, {%0,%1,%2,%3};"
        : "+f"(d[0]), "+f"(d[1]), "+f"(d[2]), "+f"(d[3])
        : "r"(a[0]), "r"(a[1]), "r"(a[2]), "r"(a[3]), "r"(b0), "r"(b1));
}

// smem map (offsets from 1024-aligned base)
#define SM_A    0u           // 128 x 256 fp16 = 64KB (512B rows, swizzled)
#define SM_B    65536u       // 2 x 64KB B chunks (256 rows x 128 fp16, 256B rows)
// epilogue reduction scratch
#define SM_RF   196608u              // float[4 wn][128] row expsum
#define SM_RV   (SM_RF + 2048u)
#define SM_RC   (SM_RV + 2048u)
#define SM_CF   (SM_RC + 2048u)      // float[4 wm][256] col expsum
#define SM_CV   (SM_CF + 4096u)
#define SM_CC   (SM_CV + 4096u)
#define SMEM_BYTES (215040 + 1024)

// ---------------- kernel 1: normalize + fp16 convert ----------------
__global__ void normalize_kernel(const float* __restrict__ z1,
                                 const float* __restrict__ z2) {
    if (blockIdx.x == 0 && threadIdx.x == 0) g_ctr = 0;   // reset finalize counter
    int row  = blockIdx.x * 8 + (threadIdx.x >> 5);
    int lane = threadIdx.x & 31;
    const float* src = (row < N_HALF) ? (z1 + (size_t)row * Dm)
                                      : (z2 + (size_t)(row - N_HALF) * Dm);
    float4 a = *reinterpret_cast<const float4*>(src + lane * 8);
    float4 b = *reinterpret_cast<const float4*>(src + lane * 8 + 4);
    float s = a.x*a.x + a.y*a.y + a.z*a.z + a.w*a.w
            + b.x*b.x + b.y*b.y + b.z*b.z + b.w*b.w;
    #pragma unroll
    for (int off = 16; off > 0; off >>= 1)
        s += __shfl_xor_sync(0xffffffffu, s, off);
    float sc = 1.0f / fmaxf(sqrtf(s), EPSN);
    float v[8] = {a.x*sc, a.y*sc, a.z*sc, a.w*sc, b.x*sc, b.y*sc, b.z*sc, b.w*sc};
    union { __half h[8]; uint4 u; } H;
    #pragma unroll
    for (int i = 0; i < 8; i++) H.h[i] = __float2half_rn(v[i]);
    *reinterpret_cast<uint4*>((uint8_t*)gF + (size_t)row * 512 + lane * 16) = H.u;
}

// ---------------- kernel 2: persistent symmetric fp16 HMMA, 128x256 pair-tiles
// 148 persistent CTAs; bi-major pair ranges; A panel (block bi) reloaded on bi
// change. 16 warps (512 thr): wm = wid&3 (32-row), wn = wid>>2 (64-col of 256).
// B pair-tile streamed as two K=128 chunks (64KB), double-buffered.
__global__ void __launch_bounds__(512, 1)
sim_hmma_kernel(const float* __restrict__ lt) {
    extern __shared__ char smraw[];
    uint32_t sb0 = smem_u32(smraw);
    uint32_t sb  = (sb0 + 1023u) & ~1023u;
    char* smb    = smraw + (sb - sb0);

    const int tid  = threadIdx.x;
    const int lane = tid & 31;
    const int wid  = tid >> 5;
    const int wm   = wid & 3;
    const int wn   = wid >> 2;

    const int cta = blockIdx.x;
    const int p0  = (cta * NPAIR) / GRID;
    const int p1  = ((cta + 1) * NPAIR) / GRID;

    const float invT = expf(-lt[0]);

    // decode starting (bi, k): pairs(b) = 32 - b/2; pj = bi + 2k
    int bi = 0, cum = 0;
    while (cum + (32 - (bi >> 1)) <= p0) { cum += 32 - (bi >> 1); bi++; }
    int k  = p0 - cum;
    int pj = bi + 2 * k;

    // load cursor (independent copy)
    int ld_bi = bi, ld_k = k, ld_pj = pj, ld_h = 0, ld_cnt = 0;
    const int totalChunks = (p1 - p0) * 2;

    const uint32_t a_lo = (lane & 15) * 512u + (lane >> 4) * 16u;
    const uint32_t b_lo = (lane & 15) * 256u + (lane >> 4) * 16u;
    const uint32_t lxr  = (uint32_t)(lane & 7) << 4;
    const uint32_t Ab   = sb + SM_A + wm * 16384u;     // wm*32 rows * 512B

    auto loadA = [&](int bib) {
        int u = tid;
        #pragma unroll
        for (int i = 0; i < 8; i++, u += 512) {
            int rr = u >> 5, ku = u & 31;
            const uint8_t* gsrc = (const uint8_t*)gF + ((size_t)(bib * 128 + rr)) * 512 + ku * 16;
            uint32_t sdst = (sb + SM_A + (uint32_t)(rr * 512 + ku * 16))
                            ^ (uint32_t)((rr & 7) << 4);
            cp16(sdst, gsrc);
        }
        cp_commit();
    };
    auto issueB = [&]() {     // one 64KB chunk: 256 rows x 256B (K=128, half ld_h)
        const uint32_t st = (uint32_t)(ld_cnt & 1);
        int u = tid;
        #pragma unroll
        for (int i = 0; i < 8; i++, u += 512) {
            int rr = u >> 4, ku = u & 15;
            int grow = ld_pj * 128 + rr;
            if (grow >= N2) grow -= 128;               // clamp (duplicate) for odd tail
            const uint8_t* gsrc = (const uint8_t*)gF + (size_t)grow * 512 + ld_h * 256 + ku * 16;
            uint32_t sdst = (sb + SM_B + st * 65536u + (uint32_t)(rr * 256 + ku * 16))
                            ^ (uint32_t)((rr & 7) << 4);
            cp16(sdst, gsrc);
        }
        cp_commit();
        ld_cnt++;
        if (++ld_h == 2) {
            ld_h = 0; ld_k++; ld_pj += 2;
            if (ld_k == 32 - (ld_bi >> 1)) { ld_bi++; ld_k = 0; ld_pj = ld_bi; }
        }
    };

    int c = 0;
    loadA(bi); int bi_loaded = bi;
    issueB();                               // chunk 0

    for (int p = p0; p < p1; p++) {
        if (bi != bi_loaded) { loadA(bi); bi_loaded = bi; }

        float acc[2][8][4];
        #pragma unroll
        for (int mf = 0; mf < 2; mf++)
            #pragma unroll
            for (int nf = 0; nf < 8; nf++)
                #pragma unroll
                for (int v = 0; v < 4; v++) acc[mf][nf][v] = 0.0f;

        #pragma unroll
        for (int h = 0; h < 2; h++) {
            cp_wait0();
            __syncthreads();
            if (ld_cnt < totalChunks) issueB();    // prefetch next chunk

            const uint32_t Bw = sb + SM_B + (uint32_t)(c & 1) * 65536u + wn * 16384u;
            #pragma unroll
            for (int kk = 0; kk < 128; kk += 16) {
                uint32_t bfr[4][4], af[2][4];
                #pragma unroll
                for (int nb = 0; nb < 4; nb++)
                    ldm_x4(bfr[nb], (Bw + nb * 4096u + kk * 2u + b_lo) ^ lxr);
                const uint32_t kA2 = (uint32_t)(h * 128 + kk) * 2u;
                ldm_x4(af[0], (Ab + 0u    + kA2 + a_lo) ^ lxr);
                ldm_x4(af[1], (Ab + 8192u + kA2 + a_lo) ^ lxr);
                #pragma unroll
                for (int mf = 0; mf < 2; mf++)
                    #pragma unroll
                    for (int nb = 0; nb < 4; nb++) {
                        mma16816(acc[mf][nb*2  ], af[mf], bfr[nb][0], bfr[nb][2]);
                        mma16816(acc[mf][nb*2+1], af[mf], bfr[nb][1], bfr[nb][3]);
                    }
            }
            c++;
        }

        // ============== epilogue: dual-direction reduction ==============
        const int  lq   = lane >> 2;
        const int  hf   = wn >> 1;            // which bj half this warp is in
        const int  wnl  = wn & 1;
        const int  bje  = pj + hf;
        const bool valid   = (bje < NBLK);
        const bool isDiagW = valid && (bje == bi);
        const bool isTgtW  = valid && (bje == bi + 32);

        float fsum[4], mv[4];   int mc[4];    // row direction (4 row slots)
        float csum[16], cv[16]; int cim[16];  // col direction (16 col slots)
        #pragma unroll
        for (int s = 0; s < 4; s++)  { fsum[s] = 0.0f; mv[s] = -INFINITY; mc[s] = 0; }
        #pragma unroll
        for (int cc2 = 0; cc2 < 16; cc2++) { csum[cc2] = 0.0f; cv[cc2] = -INFINITY; cim[cc2] = 0; }

        #pragma unroll
        for (int mf = 0; mf < 2; mf++)
            #pragma unroll
            for (int nf = 0; nf < 8; nf++)
                #pragma unroll
                for (int v = 0; v < 4; v++) {
                    const int rl  = wm * 32 + mf * 16 + lq + (v >> 1) * 8;
                    const int clh = wnl * 64 + nf * 8 + (lane & 3) * 2 + (v & 1);
                    const float sv = acc[mf][nf][v];
                    const float e  = __expf((sv - 1.0f) * invT);
                    const bool same = (rl == clh);
                    if (isTgtW && same) {
                        const float tv = sv * invT;
                        g_tgt[bi * 128 + rl]        = tv;
                        g_tgt[bi * 128 + rl + 4096] = tv;
                    }
                    if (valid && !(isDiagW && same)) {
                        const int s   = mf * 2 + (v >> 1);
                        const int cc3 = nf * 2 + (v & 1);
                        fsum[s] += e;
                        if (sv > mv[s]) { mv[s] = sv; mc[s] = clh; }
                        csum[cc3] += e;
                        if (sv > cv[cc3]) { cv[cc3] = sv; cim[cc3] = rl; }
                    }
                }

        // row dir: quad shfl reduce (over lane&3)
        #pragma unroll
        for (int s = 0; s < 4; s++) {
            #pragma unroll
            for (int o = 1; o < 4; o <<= 1) {
                float of = __shfl_xor_sync(0xffffffffu, fsum[s], o);
                float ov = __shfl_xor_sync(0xffffffffu, mv[s],   o);
                int   oc = __shfl_xor_sync(0xffffffffu, mc[s],   o);
                fsum[s] += of;
                if (ov > mv[s] || (ov == mv[s] && oc < mc[s])) { mv[s] = ov; mc[s] = oc; }
            }
        }
        if ((lane & 3) == 0) {
            #pragma unroll
            for (int s = 0; s < 4; s++) {
                const int rl = wm * 32 + s * 8 + lq;
                *(float*)(smb + SM_RF + (wn * 128 + rl) * 4) = fsum[s];
                *(float*)(smb + SM_RV + (wn * 128 + rl) * 4) = mv[s];
                *(int*)  (smb + SM_RC + (wn * 128 + rl) * 4) = mc[s];
            }
        }
        // col dir: shfl reduce over lq (xor 4,8,16)
        #pragma unroll
        for (int cc2 = 0; cc2 < 16; cc2++) {
            #pragma unroll
            for (int o = 4; o < 32; o <<= 1) {
                float of = __shfl_xor_sync(0xffffffffu, csum[cc2], o);
                float ov = __shfl_xor_sync(0xffffffffu, cv[cc2],   o);
                int   oi = __shfl_xor_sync(0xffffffffu, cim[cc2],  o);
                csum[cc2] += of;
                if (ov > cv[cc2] || (ov == cv[cc2] && oi < cim[cc2])) { cv[cc2] = ov; cim[cc2] = oi; }
            }
        }
        if (lane < 4) {
            #pragma unroll
            for (int cc2 = 0; cc2 < 16; cc2++) {
                const int cl256 = wn * 64 + (cc2 >> 1) * 8 + lane * 2 + (cc2 & 1);
                *(float*)(smb + SM_CF + (wm * 256 + cl256) * 4) = csum[cc2];
                *(float*)(smb + SM_CV + (wm * 256 + cl256) * 4) = cv[cc2];
                *(int*)  (smb + SM_CC + (wm * 256 + cl256) * 4) = cim[cc2];
            }
        }
        __syncthreads();

        if (tid < 128) {     // row direction: combine wn halves per bj block
            const int rl = tid;
            #pragma unroll
            for (int hh = 0; hh < 2; hh++) {
                const int bj2 = pj + hh;
                if (bj2 < NBLK) {
                    float f = 0.0f, bv = -INFINITY; int bc = 0;
                    #pragma unroll
                    for (int w = 0; w < 2; w++) {
                        const int ws = hh * 2 + w;
                        f += *(float*)(smb + SM_RF + (ws * 128 + rl) * 4);
                        float v2 = *(float*)(smb + SM_RV + (ws * 128 + rl) * 4);
                        int   c2 = *(int*)  (smb + SM_RC + (ws * 128 + rl) * 4);
                        if (v2 > bv) { bv = v2; bc = c2; }
                    }
                    const int row = bi * 128 + rl;
                    g_pf [bj2][row] = f;
                    g_pmv[bj2][row] = bv;
                    g_pmc[bj2][row] = bj2 * 128 + bc;
                }
            }
        }
        if (tid < 256) {     // col direction -> rows of block bje2, slot bi
            const int hh  = tid >> 7;
            const int cl  = tid & 127;
            const int bj2 = pj + hh;
            if (bj2 < NBLK && bj2 != bi) {
                float f = 0.0f, bv = -INFINITY; int br = 0;
                #pragma unroll
                for (int w = 0; w < 4; w++) {
                    const int idx = w * 256 + hh * 128 + cl;
                    f += *(float*)(smb + SM_CF + idx * 4);
                    float v2 = *(float*)(smb + SM_CV + idx * 4);
                    int   r2 = *(int*)  (smb + SM_CC + idx * 4);
                    if (v2 > bv) { bv = v2; br = r2; }
                }
                const int row = bj2 * 128 + cl;
                g_pf [bi][row] = f;
                g_pmv[bi][row] = bv;
                g_pmc[bi][row] = bi * 128 + br;
            }
        }

        // advance pair
        k++; pj += 2;
        if (k == 32 - (bi >> 1)) { bi++; k = 0; pj = bi; }
    }
}

// ------- kernel 3: per-row reduce over 64 slots + last-block final scalar ---
__global__ void finalize_kernel(const float* __restrict__ lt, float* __restrict__ out) {
    __shared__ float sl[256];
    __shared__ int   sc[256];
    __shared__ int   isLast;
    const int tid = threadIdx.x;
    const int row = blockIdx.x * 256 + tid;
    const float invT = expf(-lt[0]);
    float fs = 0.0f, bv = -INFINITY;
    int bc = -1;
    #pragma unroll 8
    for (int o = 0; o < NBLK; o++) {
        fs += g_pf[o][row];
        float v = g_pmv[o][row];
        int   c = g_pmc[o][row];
        if (v > bv || (v == bv && c < bc)) { bv = v; bc = c; }
    }
    float lse = invT + logf(fs);
    sl[tid] = lse - g_tgt[row];
    sc[tid] = (bc == (row ^ 4096)) ? 1 : 0;
    __syncthreads();
    for (int s = 128; s > 0; s >>= 1) {
        if (tid < s) { sl[tid] += sl[tid + s]; sc[tid] += sc[tid + s]; }
        __syncthreads();
    }
    if (tid == 0) {
        g_redl[blockIdx.x] = sl[0];
        g_redc[blockIdx.x] = sc[0];
        __threadfence();
        isLast = (atomicAdd(&g_ctr, 1) == 31);
    }
    __syncthreads();
    if (isLast && tid < 32) {
        float l = g_redl[tid];
        int   c = g_redc[tid];
        #pragma unroll
        for (int o = 16; o > 0; o >>= 1) {
            l += __shfl_xor_sync(0xffffffffu, l, o);
            c += __shfl_xor_sync(0xffffffffu, c, o);
        }
        if (tid == 0) {
            out[0] = l / (float)N2;
            out[1] = 0.5f * (float)c;
        }
    }
}

extern "C" void kernel_launch(void* const* d_in, const int* in_sizes, int n_in,
                              void* d_out, int out_size) {
    const float* z1 = (const float*)d_in[0];
    const float* z2 = (const float*)d_in[1];
    const float* lt = (const float*)d_in[2];
    float* out = (float*)d_out;

    cudaFuncSetAttribute(sim_hmma_kernel,
                         cudaFuncAttributeMaxDynamicSharedMemorySize, SMEM_BYTES);

    normalize_kernel<<<N2 / 8, 256>>>(z1, z2);
    sim_hmma_kernel<<<GRID, 512, SMEM_BYTES>>>(lt);
    finalize_kernel<<<32, 256>>>(lt, out);
}